// round 12
// baseline (speedup 1.0000x reference)
#include <cuda_runtime.h>
#include <cuda_bf16.h>
#include <math.h>
#include <stdint.h>

#define NN 4096
#define DD 256

// ---------------- scratch (static device globals; no allocation) ----------------
__device__ float          g_h[NN * DD];          // 4 MB : h fp32
__device__ __nv_bfloat16  g_hb[NN * DD];         // 2 MB : h bf16 [j][d] (B operand)
__device__ __nv_bfloat16  g_Wb[(size_t)NN * NN]; // 32 MB: combined attention weights bf16
__device__ float4 g_wh1[NN];
__device__ float4 g_wh2[NN];
__device__ float4 g_e2[NN];                      // exp(wh2 - m2) per head
__device__ float  g_hp[4][NN * DD];              // 16 MB: split-K partials
__device__ float  g_max[8];

// ---------------- helpers ----------------
__device__ __forceinline__ void atomicMaxF(float* addr, float v) {
    int old = __float_as_int(*addr);
    while (__int_as_float(old) < v) {
        int assumed = old;
        old = atomicCAS((int*)addr, assumed, __float_as_int(v));
        if (old == assumed) break;
    }
}
__device__ __forceinline__ uint32_t smem_u32(const void* p) {
    uint32_t a;
    asm("{ .reg .u64 t; cvta.to.shared.u64 t, %1; cvt.u32.u64 %0, t; }" : "=r"(a) : "l"(p));
    return a;
}
__device__ __forceinline__ void cpasync16(uint32_t dst, const void* src) {
    asm volatile("cp.async.cg.shared.global [%0], [%1], 16;" :: "r"(dst), "l"(src));
}
#define CP_COMMIT()  asm volatile("cp.async.commit_group;" ::: "memory")
#define CP_WAIT(n)   asm volatile("cp.async.wait_group %0;" :: "n"(n) : "memory")
__device__ __forceinline__ void ldmA(uint32_t* r, uint32_t addr) {
    asm volatile("ldmatrix.sync.aligned.m8n8.x4.shared.b16 {%0,%1,%2,%3}, [%4];"
                 : "=r"(r[0]), "=r"(r[1]), "=r"(r[2]), "=r"(r[3]) : "r"(addr));
}
__device__ __forceinline__ void ldmBT(uint32_t* r, uint32_t addr) {
    asm volatile("ldmatrix.sync.aligned.m8n8.x4.trans.shared.b16 {%0,%1,%2,%3}, [%4];"
                 : "=r"(r[0]), "=r"(r[1]), "=r"(r[2]), "=r"(r[3]) : "r"(addr));
}
__device__ __forceinline__ void mma16816(float* c, const uint32_t* a, uint32_t b0, uint32_t b1) {
    asm volatile("mma.sync.aligned.m16n8k16.row.col.f32.bf16.bf16.f32 "
                 "{%0,%1,%2,%3}, {%4,%5,%6,%7}, {%8,%9}, {%0,%1,%2,%3};"
                 : "+f"(c[0]), "+f"(c[1]), "+f"(c[2]), "+f"(c[3])
                 : "r"(a[0]), "r"(a[1]), "r"(a[2]), "r"(a[3]), "r"(b0), "r"(b1));
}

// ---------------- kernel 0: reset maxima ----------------
__global__ void k0_init() {
    if (threadIdx.x < 8) g_max[threadIdx.x] = -3.4e38f;
}

// ---------------- kernel 1: h, h(bf16), Wh1/Wh2, maxima ----------------
__global__ void k1_prep(const float* __restrict__ x, const float* __restrict__ cw,
                        const float* __restrict__ cb, const float* __restrict__ a) {
    int i = blockIdx.x;
    int d = threadIdx.x;
    float v = x[i * DD + d] * cw[0] + cb[0];
    g_h[i * DD + d] = v;
    g_hb[i * DD + d] = __float2bfloat16_rn(v);

    float p[8];
#pragma unroll
    for (int hh = 0; hh < 4; hh++) {
        p[hh]     = v * a[hh * 2 * DD + d];
        p[4 + hh] = v * a[hh * 2 * DD + DD + d];
    }
#pragma unroll
    for (int q = 0; q < 8; q++)
#pragma unroll
        for (int o = 16; o > 0; o >>= 1)
            p[q] += __shfl_xor_sync(0xffffffffu, p[q], o);

    __shared__ float red[8][8];
    int w = d >> 5, lane = d & 31;
    if (lane == 0) {
#pragma unroll
        for (int q = 0; q < 8; q++) red[w][q] = p[q];
    }
    __syncthreads();
    if (d < 8) {
        int q = d;
        float s = 0.f;
#pragma unroll
        for (int ww = 0; ww < 8; ww++) s += red[ww][q];
        if (q < 4) ((float*)g_wh1)[i * 4 + q] = s;
        else       ((float*)g_wh2)[i * 4 + (q - 4)] = s;
        atomicMaxF(&g_max[q], s);
    }
}

// ---------------- kernel 1b: E2[j,h] = exp(wh2[j,h] - m2[h]) ----------------
__global__ void __launch_bounds__(256) k1b_e2() {
    int j = blockIdx.x * 256 + threadIdx.x;
    float4 t2 = g_wh2[j];
    float4 e;
    e.x = __expf(t2.x - g_max[4]);
    e.y = __expf(t2.y - g_max[5]);
    e.z = __expf(t2.z - g_max[6]);
    e.w = __expf(t2.w - g_max[7]);
    g_e2[j] = e;
}

// ---------------- kernel 2: W[i,j] = 1/4 sum_h softmax (factorized exp) ----------------
// 512 threads, 8 j's per thread, fp32 cache tc[4][8] (32 regs).
// term T = exp(elu(s)-M), s = wh1+wh2, M = m1+m2:
//   p = E1*E2 = exp(s-M);  s>0 (p>exp(-M)):  T = p
//   s<=0:                 T = exp(exp(s)-1-M) = C*exp(p*exp(M)),  C = exp(-1-M)
__global__ void __launch_bounds__(512) k2_weights(const int* __restrict__ adj) {
    int i   = blockIdx.x;
    int tid = threadIdx.x;
    int lane = tid & 31, w = tid >> 5;
    __shared__ float red[16][4];
    __shared__ float Sinv[4];

    float4 t1 = g_wh1[i];
    float wh1[4] = {t1.x, t1.y, t1.z, t1.w};
    float e1[4], expM[4], Cc[4], pth[4];
#pragma unroll
    for (int hh = 0; hh < 4; hh++) {
        float m1 = g_max[hh], m2 = g_max[4 + hh];
        float M = m1 + m2;
        e1[hh]   = __expf(wh1[hh] - m1);
        expM[hh] = __expf(M);
        Cc[hh]   = __expf(-1.f - M);
        pth[hh]  = __expf(-M);
    }
    const int* arow = adj + i * NN;

    // pass A: compute all masked terms once, cache fp32 (this thread owns j = tid*8..tid*8+7)
    float tc[4][8];
    float sm[4] = {0.f, 0.f, 0.f, 0.f};
#pragma unroll
    for (int it = 0; it < 2; it++) {
        int jb = tid * 8 + it * 4;
        int4 av = *(const int4*)(arow + jb);
        int aa[4] = {av.x, av.y, av.z, av.w};
#pragma unroll
        for (int u = 0; u < 4; u++) {
            float4 ev = g_e2[jb + u];
            float e2[4] = {ev.x, ev.y, ev.z, ev.w};
#pragma unroll
            for (int hh = 0; hh < 4; hh++) {
                float p  = e1[hh] * e2[hh];
                float tn = Cc[hh] * __expf(p * expM[hh]);   // negative branch
                float t  = p > pth[hh] ? p : tn;
                t = aa[u] > 0 ? t : 0.f;
                tc[hh][it * 4 + u] = t;
                sm[hh] += t;
            }
        }
    }
#pragma unroll
    for (int hh = 0; hh < 4; hh++)
#pragma unroll
        for (int o = 16; o > 0; o >>= 1)
            sm[hh] += __shfl_xor_sync(0xffffffffu, sm[hh], o);
    if (lane == 0) {
        red[w][0] = sm[0]; red[w][1] = sm[1]; red[w][2] = sm[2]; red[w][3] = sm[3];
    }
    __syncthreads();
    if (tid < 4) {
        float s = 0.f;
#pragma unroll
        for (int ww = 0; ww < 16; ww++) s += red[ww][tid];
        Sinv[tid] = 0.25f / s;
    }
    __syncthreads();
    float inv[4] = {Sinv[0], Sinv[1], Sinv[2], Sinv[3]};

    // pass B: combine cached terms, write bf16 (8 contiguous per thread)
#pragma unroll
    for (int it = 0; it < 2; it++) {
        int jb = tid * 8 + it * 4;
        float res[4];
#pragma unroll
        for (int u = 0; u < 4; u++) {
            int li = it * 4 + u;
            res[u] = tc[0][li] * inv[0] + tc[1][li] * inv[1] +
                     tc[2][li] * inv[2] + tc[3][li] * inv[3];
        }
        __nv_bfloat162 r0 = __floats2bfloat162_rn(res[0], res[1]);
        __nv_bfloat162 r1 = __floats2bfloat162_rn(res[2], res[3]);
        uint2 pk = make_uint2(*(uint32_t*)&r0, *(uint32_t*)&r1);
        *(uint2*)&g_Wb[(size_t)i * NN + jb] = pk;
    }
}

// ---------------- kernel 3: bf16 mma.sync GEMM, cp.async 3-stage, split-K=4 ----------------
// BM=64, BN=64, BK=32; 256 threads (8 warps in 2x4). grid (64, 4, 4) = 1024 CTAs.
// Each split-z handles K range [z*1024, (z+1)*1024) and stores raw partials.
#define BK 32
#define NSTAGE 3
#define A_STRIDE 40   // bf16 elems per row (32 + 8 pad) -> 80B
#define B_STRIDE 72   // bf16 elems per row (64 + 8 pad) -> 144B

__global__ void __launch_bounds__(256) k3_gemm() {
    __shared__ __nv_bfloat16 As[NSTAGE][64][A_STRIDE];
    __shared__ __nv_bfloat16 Bs[NSTAGE][BK][B_STRIDE];
    int tid = threadIdx.x;
    int w = tid >> 5, lane = tid & 31;
    int wr = w >> 2, wc = w & 3;
    int row0 = blockIdx.x * 64;
    int col0 = blockIdx.y * 64;
    int kbase = blockIdx.z * (NN / 4);

    float acc[2][2][4];
#pragma unroll
    for (int mt = 0; mt < 2; mt++)
#pragma unroll
        for (int nt = 0; nt < 2; nt++)
#pragma unroll
            for (int q = 0; q < 4; q++) acc[mt][nt][q] = 0.f;

    int ar = tid >> 2, aq = tid & 3;
    int br = tid >> 3, bq = tid & 7;

    uint32_t sA[NSTAGE], sB[NSTAGE];
#pragma unroll
    for (int s = 0; s < NSTAGE; s++) {
        sA[s] = smem_u32(&As[s][ar][aq * 8]);
        sB[s] = smem_u32(&Bs[s][br][bq * 8]);
    }

    const int NKS = (NN / 4) / BK;   // 32

#define LOAD_TILE(s, t)                                                           \
    do {                                                                          \
        int k0_ = kbase + (t) * BK;                                               \
        cpasync16(sA[s], &g_Wb[(size_t)(row0 + ar) * NN + k0_ + aq * 8]);         \
        cpasync16(sB[s], &g_hb[(size_t)(k0_ + br) * DD + col0 + bq * 8]);         \
    } while (0)

    LOAD_TILE(0, 0); CP_COMMIT();
    LOAD_TILE(1, 1); CP_COMMIT();

    for (int t = 0; t < NKS; t++) {
        CP_WAIT(1);
        __syncthreads();

        int nxt = t + 2;
        if (nxt < NKS) { LOAD_TILE(nxt % NSTAGE, nxt); }
        CP_COMMIT();

        int buf = t % NSTAGE;
#pragma unroll
        for (int ks = 0; ks < 2; ks++) {
            uint32_t a[2][4];
#pragma unroll
            for (int mt = 0; mt < 2; mt++)
                ldmA(a[mt], smem_u32(&As[buf][wr * 32 + mt * 16 + (lane & 15)]
                                            [ks * 16 + (lane >> 4) * 8]));
            uint32_t b[4];
            ldmBT(b, smem_u32(&Bs[buf][ks * 16 + (lane & 15)]
                                      [wc * 16 + (lane >> 4) * 8]));
#pragma unroll
            for (int mt = 0; mt < 2; mt++)
#pragma unroll
                for (int nt = 0; nt < 2; nt++)
                    mma16816(acc[mt][nt], a[mt], b[nt * 2], b[nt * 2 + 1]);
        }
    }
#undef LOAD_TILE

    // store raw partials (no epilogue)
    float* dst = g_hp[blockIdx.z];
#pragma unroll
    for (int mt = 0; mt < 2; mt++) {
        int rT = row0 + wr * 32 + mt * 16 + (lane >> 2);
        int rB = rT + 8;
#pragma unroll
        for (int nt = 0; nt < 2; nt++) {
            int c = col0 + wc * 16 + nt * 8 + (lane & 3) * 2;
            *(float2*)&dst[rT * DD + c] = make_float2(acc[mt][nt][0], acc[mt][nt][1]);
            *(float2*)&dst[rB * DD + c] = make_float2(acc[mt][nt][2], acc[mt][nt][3]);
        }
    }
}

// ---------------- kernel 4: epilogue (sum partials, elu, row L2-norm, bias) ----------------
__global__ void __launch_bounds__(256) k4_norm(const float* __restrict__ bias,
                                               float* __restrict__ out) {
    __shared__ float red[8];
    __shared__ float s_inv;
    int r = blockIdx.x;
    int c = threadIdx.x;
    int lane = c & 31, w = c >> 5;
    int idx = r * DD + c;

    float hp = (g_hp[0][idx] + g_hp[1][idx]) + (g_hp[2][idx] + g_hp[3][idx]);
    float o = 0.5f * (hp + g_h[idx]);
    o = o > 0.f ? o : (__expf(o) - 1.f);

    float sq = o * o;
#pragma unroll
    for (int off = 16; off > 0; off >>= 1)
        sq += __shfl_xor_sync(0xffffffffu, sq, off);
    if (lane == 0) red[w] = sq;
    __syncthreads();
    if (c < 8) {
        float s = red[c];
#pragma unroll
        for (int off = 4; off > 0; off >>= 1)
            s += __shfl_xor_sync(0xffu, s, off);
        if (c == 0) s_inv = 1.0f / fmaxf(sqrtf(s), 1e-12f);
    }
    __syncthreads();
    out[idx] = o * s_inv + bias[c];
}

// ---------------- launch ----------------
extern "C" void kernel_launch(void* const* d_in, const int* in_sizes, int n_in,
                              void* d_out, int out_size) {
    const float* x    = (const float*)d_in[0];
    const int*   adj  = (const int*)d_in[1];
    const float* cw   = (const float*)d_in[2];
    const float* cb   = (const float*)d_in[3];
    const float* a    = (const float*)d_in[4];
    const float* bias = (const float*)d_in[5];
    float* out = (float*)d_out;

    k0_init<<<1, 32>>>();
    k1_prep<<<NN, 256>>>(x, cw, cb, a);
    k1b_e2<<<NN / 256, 256>>>();
    k2_weights<<<NN, 512>>>(adj);
    dim3 g3(NN / 64, DD / 64, 4);
    k3_gemm<<<g3, 256>>>();
    k4_norm<<<NN, 256>>>(bias, out);
}

// round 15
// speedup vs baseline: 1.2886x; 1.2886x over previous
#include <cuda_runtime.h>
#include <cuda_bf16.h>
#include <cuda_fp16.h>
#include <math.h>
#include <stdint.h>

#define NN 4096
#define DD 256

// ---------------- scratch (static device globals; no allocation) ----------------
__device__ float          g_h[NN * DD];          // 4 MB : h fp32
__device__ __nv_bfloat16  g_hb[NN * DD];         // 2 MB : h bf16 [j][d] (B operand)
__device__ __nv_bfloat16  g_Wb[(size_t)NN * NN]; // 32 MB: combined attention weights bf16
__device__ float4 g_wh1[NN];
__device__ float4 g_wh2[NN];
__device__ float4 g_e2[NN];                      // exp(wh2 - m2) per head
__device__ float  g_hp[4][NN * DD];              // 16 MB: split-K partials
__device__ float  g_max[8];

// ---------------- helpers ----------------
__device__ __forceinline__ void atomicMaxF(float* addr, float v) {
    int old = __float_as_int(*addr);
    while (__int_as_float(old) < v) {
        int assumed = old;
        old = atomicCAS((int*)addr, assumed, __float_as_int(v));
        if (old == assumed) break;
    }
}
__device__ __forceinline__ uint32_t smem_u32(const void* p) {
    uint32_t a;
    asm("{ .reg .u64 t; cvta.to.shared.u64 t, %1; cvt.u32.u64 %0, t; }" : "=r"(a) : "l"(p));
    return a;
}
__device__ __forceinline__ void cpasync16(uint32_t dst, const void* src) {
    asm volatile("cp.async.cg.shared.global [%0], [%1], 16;" :: "r"(dst), "l"(src));
}
#define CP_COMMIT()  asm volatile("cp.async.commit_group;" ::: "memory")
#define CP_WAIT(n)   asm volatile("cp.async.wait_group %0;" :: "n"(n) : "memory")
__device__ __forceinline__ void ldmA(uint32_t* r, uint32_t addr) {
    asm volatile("ldmatrix.sync.aligned.m8n8.x4.shared.b16 {%0,%1,%2,%3}, [%4];"
                 : "=r"(r[0]), "=r"(r[1]), "=r"(r[2]), "=r"(r[3]) : "r"(addr));
}
__device__ __forceinline__ void ldmBT(uint32_t* r, uint32_t addr) {
    asm volatile("ldmatrix.sync.aligned.m8n8.x4.trans.shared.b16 {%0,%1,%2,%3}, [%4];"
                 : "=r"(r[0]), "=r"(r[1]), "=r"(r[2]), "=r"(r[3]) : "r"(addr));
}
__device__ __forceinline__ void mma16816(float* c, const uint32_t* a, uint32_t b0, uint32_t b1) {
    asm volatile("mma.sync.aligned.m16n8k16.row.col.f32.bf16.bf16.f32 "
                 "{%0,%1,%2,%3}, {%4,%5,%6,%7}, {%8,%9}, {%0,%1,%2,%3};"
                 : "+f"(c[0]), "+f"(c[1]), "+f"(c[2]), "+f"(c[3])
                 : "r"(a[0]), "r"(a[1]), "r"(a[2]), "r"(a[3]), "r"(b0), "r"(b1));
}

// ---------------- kernel 0: reset maxima ----------------
__global__ void k0_init() {
    if (threadIdx.x < 8) g_max[threadIdx.x] = -3.4e38f;
}

// ---------------- kernel 1: h, h(bf16), Wh1/Wh2, maxima ----------------
__global__ void k1_prep(const float* __restrict__ x, const float* __restrict__ cw,
                        const float* __restrict__ cb, const float* __restrict__ a) {
    int i = blockIdx.x;
    int d = threadIdx.x;
    float v = x[i * DD + d] * cw[0] + cb[0];
    g_h[i * DD + d] = v;
    g_hb[i * DD + d] = __float2bfloat16_rn(v);

    float p[8];
#pragma unroll
    for (int hh = 0; hh < 4; hh++) {
        p[hh]     = v * a[hh * 2 * DD + d];
        p[4 + hh] = v * a[hh * 2 * DD + DD + d];
    }
#pragma unroll
    for (int q = 0; q < 8; q++)
#pragma unroll
        for (int o = 16; o > 0; o >>= 1)
            p[q] += __shfl_xor_sync(0xffffffffu, p[q], o);

    __shared__ float red[8][8];
    int w = d >> 5, lane = d & 31;
    if (lane == 0) {
#pragma unroll
        for (int q = 0; q < 8; q++) red[w][q] = p[q];
    }
    __syncthreads();
    if (d < 8) {
        int q = d;
        float s = 0.f;
#pragma unroll
        for (int ww = 0; ww < 8; ww++) s += red[ww][q];
        if (q < 4) ((float*)g_wh1)[i * 4 + q] = s;
        else       ((float*)g_wh2)[i * 4 + (q - 4)] = s;
        atomicMaxF(&g_max[q], s);
    }
}

// ---------------- kernel 1b: E2[j,h] = exp(wh2[j,h] - m2[h]) ----------------
__global__ void __launch_bounds__(256) k1b_e2() {
    int j = blockIdx.x * 256 + threadIdx.x;
    float4 t2 = g_wh2[j];
    float4 e;
    e.x = __expf(t2.x - g_max[4]);
    e.y = __expf(t2.y - g_max[5]);
    e.z = __expf(t2.z - g_max[6]);
    e.w = __expf(t2.w - g_max[7]);
    g_e2[j] = e;
}

// ---------------- kernel 2: W[i,j] = 1/4 sum_h softmax (factorized exp) ----------------
// 256 threads, 16 j's per thread (coalesced layout jb = tid*4 + it*1024).
// fp16 term cache with CONSISTENT normalizer: sm accumulated from the fp16-rounded
// values, so softmax weights still sum to exactly 1 (rounding acts as logit noise).
// term T = exp(elu(s)-M), s = wh1+wh2, M = m1+m2:
//   p = E1*E2 = exp(s-M);  s>0 (p>exp(-M)):  T = p
//   s<=0:                 T = exp(exp(s)-1-M) = C*exp(p*exp(M)),  C = exp(-1-M)
__global__ void __launch_bounds__(256) k2_weights(const int* __restrict__ adj) {
    int i   = blockIdx.x;
    int tid = threadIdx.x;
    int lane = tid & 31, w = tid >> 5;
    __shared__ float red[8][4];
    __shared__ float Sinv[4];

    float4 t1 = g_wh1[i];
    float wh1[4] = {t1.x, t1.y, t1.z, t1.w};
    float e1[4], expM[4], Cc[4], pth[4];
#pragma unroll
    for (int hh = 0; hh < 4; hh++) {
        float m1 = g_max[hh], m2 = g_max[4 + hh];
        float M = m1 + m2;
        e1[hh]   = __expf(wh1[hh] - m1);
        expM[hh] = __expf(M);
        Cc[hh]   = __expf(-1.f - M);
        pth[hh]  = __expf(-M);
    }
    const int* arow = adj + i * NN;

    // pass A: compute all masked terms once, cache as fp16 pairs; sum the ROUNDED values
    __half2 tch[4][8];
    float sm[4] = {0.f, 0.f, 0.f, 0.f};
#pragma unroll
    for (int it = 0; it < 4; it++) {
        int jb = tid * 4 + it * 1024;
        int4 av = *(const int4*)(arow + jb);
        int aa[4] = {av.x, av.y, av.z, av.w};
        float tt[4][4];
#pragma unroll
        for (int u = 0; u < 4; u++) {
            float4 ev = g_e2[jb + u];
            float e2[4] = {ev.x, ev.y, ev.z, ev.w};
#pragma unroll
            for (int hh = 0; hh < 4; hh++) {
                float p  = e1[hh] * e2[hh];
                float tn = Cc[hh] * __expf(p * expM[hh]);   // negative branch
                float t  = p > pth[hh] ? p : tn;
                tt[hh][u] = aa[u] > 0 ? t : 0.f;
            }
        }
#pragma unroll
        for (int hh = 0; hh < 4; hh++) {
            __half2 h0 = __floats2half2_rn(tt[hh][0], tt[hh][1]);
            __half2 h1 = __floats2half2_rn(tt[hh][2], tt[hh][3]);
            tch[hh][it * 2 + 0] = h0;
            tch[hh][it * 2 + 1] = h1;
            float2 f0 = __half22float2(h0);
            float2 f1 = __half22float2(h1);
            sm[hh] += (f0.x + f0.y) + (f1.x + f1.y);   // consistent with cached values
        }
    }
#pragma unroll
    for (int hh = 0; hh < 4; hh++)
#pragma unroll
        for (int o = 16; o > 0; o >>= 1)
            sm[hh] += __shfl_xor_sync(0xffffffffu, sm[hh], o);
    if (lane == 0) {
        red[w][0] = sm[0]; red[w][1] = sm[1]; red[w][2] = sm[2]; red[w][3] = sm[3];
    }
    __syncthreads();
    if (tid < 4) {
        float s = 0.f;
#pragma unroll
        for (int ww = 0; ww < 8; ww++) s += red[ww][tid];
        Sinv[tid] = 0.25f / s;
    }
    __syncthreads();
    float inv[4] = {Sinv[0], Sinv[1], Sinv[2], Sinv[3]};

    // pass B: combine cached terms, write bf16
#pragma unroll
    for (int it = 0; it < 4; it++) {
        int jb = tid * 4 + it * 1024;
        float res[4];
#pragma unroll
        for (int pr = 0; pr < 2; pr++) {
            float2 f0 = __half22float2(tch[0][it * 2 + pr]);
            float2 f1 = __half22float2(tch[1][it * 2 + pr]);
            float2 f2 = __half22float2(tch[2][it * 2 + pr]);
            float2 f3 = __half22float2(tch[3][it * 2 + pr]);
            res[pr * 2 + 0] = f0.x * inv[0] + f1.x * inv[1] + f2.x * inv[2] + f3.x * inv[3];
            res[pr * 2 + 1] = f0.y * inv[0] + f1.y * inv[1] + f2.y * inv[2] + f3.y * inv[3];
        }
        __nv_bfloat162 r0 = __floats2bfloat162_rn(res[0], res[1]);
        __nv_bfloat162 r1 = __floats2bfloat162_rn(res[2], res[3]);
        uint2 pk = make_uint2(*(uint32_t*)&r0, *(uint32_t*)&r1);
        *(uint2*)&g_Wb[(size_t)i * NN + jb] = pk;
    }
}

// ---------------- kernel 3: bf16 mma.sync GEMM, cp.async 3-stage, split-K=4 ----------------
// BM=64, BN=64, BK=32; 256 threads (8 warps in 2x4). grid (64, 4, 4) = 1024 CTAs.
#define BK 32
#define NSTAGE 3
#define A_STRIDE 40   // bf16 elems per row (32 + 8 pad) -> 80B
#define B_STRIDE 72   // bf16 elems per row (64 + 8 pad) -> 144B

__global__ void __launch_bounds__(256) k3_gemm() {
    __shared__ __nv_bfloat16 As[NSTAGE][64][A_STRIDE];
    __shared__ __nv_bfloat16 Bs[NSTAGE][BK][B_STRIDE];
    int tid = threadIdx.x;
    int w = tid >> 5, lane = tid & 31;
    int wr = w >> 2, wc = w & 3;
    int row0 = blockIdx.x * 64;
    int col0 = blockIdx.y * 64;
    int kbase = blockIdx.z * (NN / 4);

    float acc[2][2][4];
#pragma unroll
    for (int mt = 0; mt < 2; mt++)
#pragma unroll
        for (int nt = 0; nt < 2; nt++)
#pragma unroll
            for (int q = 0; q < 4; q++) acc[mt][nt][q] = 0.f;

    int ar = tid >> 2, aq = tid & 3;
    int br = tid >> 3, bq = tid & 7;

    uint32_t sA[NSTAGE], sB[NSTAGE];
#pragma unroll
    for (int s = 0; s < NSTAGE; s++) {
        sA[s] = smem_u32(&As[s][ar][aq * 8]);
        sB[s] = smem_u32(&Bs[s][br][bq * 8]);
    }

    const int NKS = (NN / 4) / BK;   // 32

#define LOAD_TILE(s, t)                                                           \
    do {                                                                          \
        int k0_ = kbase + (t) * BK;                                               \
        cpasync16(sA[s], &g_Wb[(size_t)(row0 + ar) * NN + k0_ + aq * 8]);         \
        cpasync16(sB[s], &g_hb[(size_t)(k0_ + br) * DD + col0 + bq * 8]);         \
    } while (0)

    LOAD_TILE(0, 0); CP_COMMIT();
    LOAD_TILE(1, 1); CP_COMMIT();

    for (int t = 0; t < NKS; t++) {
        CP_WAIT(1);
        __syncthreads();

        int nxt = t + 2;
        if (nxt < NKS) { LOAD_TILE(nxt % NSTAGE, nxt); }
        CP_COMMIT();

        int buf = t % NSTAGE;
#pragma unroll
        for (int ks = 0; ks < 2; ks++) {
            uint32_t a[2][4];
#pragma unroll
            for (int mt = 0; mt < 2; mt++)
                ldmA(a[mt], smem_u32(&As[buf][wr * 32 + mt * 16 + (lane & 15)]
                                            [ks * 16 + (lane >> 4) * 8]));
            uint32_t b[4];
            ldmBT(b, smem_u32(&Bs[buf][ks * 16 + (lane & 15)]
                                      [wc * 16 + (lane >> 4) * 8]));
#pragma unroll
            for (int mt = 0; mt < 2; mt++)
#pragma unroll
                for (int nt = 0; nt < 2; nt++)
                    mma16816(acc[mt][nt], a[mt], b[nt * 2], b[nt * 2 + 1]);
        }
    }
#undef LOAD_TILE

    // store raw partials (no epilogue)
    float* dst = g_hp[blockIdx.z];
#pragma unroll
    for (int mt = 0; mt < 2; mt++) {
        int rT = row0 + wr * 32 + mt * 16 + (lane >> 2);
        int rB = rT + 8;
#pragma unroll
        for (int nt = 0; nt < 2; nt++) {
            int c = col0 + wc * 16 + nt * 8 + (lane & 3) * 2;
            *(float2*)&dst[rT * DD + c] = make_float2(acc[mt][nt][0], acc[mt][nt][1]);
            *(float2*)&dst[rB * DD + c] = make_float2(acc[mt][nt][2], acc[mt][nt][3]);
        }
    }
}

// ---------------- kernel 4: epilogue (sum partials, elu, row L2-norm, bias) ----------------
__global__ void __launch_bounds__(256) k4_norm(const float* __restrict__ bias,
                                               float* __restrict__ out) {
    __shared__ float red[8];
    __shared__ float s_inv;
    int r = blockIdx.x;
    int c = threadIdx.x;
    int lane = c & 31, w = c >> 5;
    int idx = r * DD + c;

    float hp = (g_hp[0][idx] + g_hp[1][idx]) + (g_hp[2][idx] + g_hp[3][idx]);
    float o = 0.5f * (hp + g_h[idx]);
    o = o > 0.f ? o : (__expf(o) - 1.f);

    float sq = o * o;
#pragma unroll
    for (int off = 16; off > 0; off >>= 1)
        sq += __shfl_xor_sync(0xffffffffu, sq, off);
    if (lane == 0) red[w] = sq;
    __syncthreads();
    if (c < 8) {
        float s = red[c];
#pragma unroll
        for (int off = 4; off > 0; off >>= 1)
            s += __shfl_xor_sync(0xffu, s, off);
        if (c == 0) s_inv = 1.0f / fmaxf(sqrtf(s), 1e-12f);
    }
    __syncthreads();
    out[idx] = o * s_inv + bias[c];
}

// ---------------- launch ----------------
extern "C" void kernel_launch(void* const* d_in, const int* in_sizes, int n_in,
                              void* d_out, int out_size) {
    const float* x    = (const float*)d_in[0];
    const int*   adj  = (const int*)d_in[1];
    const float* cw   = (const float*)d_in[2];
    const float* cb   = (const float*)d_in[3];
    const float* a    = (const float*)d_in[4];
    const float* bias = (const float*)d_in[5];
    float* out = (float*)d_out;

    k0_init<<<1, 32>>>();
    k1_prep<<<NN, 256>>>(x, cw, cb, a);
    k1b_e2<<<NN / 256, 256>>>();
    k2_weights<<<NN, 256>>>(adj);
    dim3 g3(NN / 64, DD / 64, 4);
    k3_gemm<<<g3, 256>>>();
    k4_norm<<<NN, 256>>>(bias, out);
}

// round 16
// speedup vs baseline: 1.6149x; 1.2532x over previous
#include <cuda_runtime.h>
#include <cuda_bf16.h>
#include <cuda_fp16.h>
#include <math.h>
#include <stdint.h>

#define NN 4096
#define DD 256

// ---------------- scratch (static device globals; no allocation) ----------------
__device__ float   g_h[NN * DD];           // 4 MB : h fp32
__device__ __half  g_hh[NN * DD];          // 2 MB : h fp16 [j][d] (B operand)
__device__ __half  g_Wh[(size_t)NN * NN];  // 32 MB: combined attention weights fp16
__device__ float4  g_wh1[NN];
__device__ float4  g_wh2[NN];
__device__ uint2   g_e2h[NN];              // e2s = exp(wh2 - m2/2), half2 x2 (heads 01, 23)
__device__ float   g_hp[4][NN * DD];       // 16 MB: split-K partials
__device__ float   g_max[8];

// ---------------- helpers ----------------
__device__ __forceinline__ void atomicMaxF(float* addr, float v) {
    int old = __float_as_int(*addr);
    while (__int_as_float(old) < v) {
        int assumed = old;
        old = atomicCAS((int*)addr, assumed, __float_as_int(v));
        if (old == assumed) break;
    }
}
__device__ __forceinline__ uint32_t smem_u32(const void* p) {
    uint32_t a;
    asm("{ .reg .u64 t; cvta.to.shared.u64 t, %1; cvt.u32.u64 %0, t; }" : "=r"(a) : "l"(p));
    return a;
}
__device__ __forceinline__ void cpasync16(uint32_t dst, const void* src) {
    asm volatile("cp.async.cg.shared.global [%0], [%1], 16;" :: "r"(dst), "l"(src));
}
#define CP_COMMIT()  asm volatile("cp.async.commit_group;" ::: "memory")
#define CP_WAIT(n)   asm volatile("cp.async.wait_group %0;" :: "n"(n) : "memory")
__device__ __forceinline__ void ldmA(uint32_t* r, uint32_t addr) {
    asm volatile("ldmatrix.sync.aligned.m8n8.x4.shared.b16 {%0,%1,%2,%3}, [%4];"
                 : "=r"(r[0]), "=r"(r[1]), "=r"(r[2]), "=r"(r[3]) : "r"(addr));
}
__device__ __forceinline__ void ldmBT(uint32_t* r, uint32_t addr) {
    asm volatile("ldmatrix.sync.aligned.m8n8.x4.trans.shared.b16 {%0,%1,%2,%3}, [%4];"
                 : "=r"(r[0]), "=r"(r[1]), "=r"(r[2]), "=r"(r[3]) : "r"(addr));
}
__device__ __forceinline__ void mma16816(float* c, const uint32_t* a, uint32_t b0, uint32_t b1) {
    asm volatile("mma.sync.aligned.m16n8k16.row.col.f32.f16.f16.f32 "
                 "{%0,%1,%2,%3}, {%4,%5,%6,%7}, {%8,%9}, {%0,%1,%2,%3};"
                 : "+f"(c[0]), "+f"(c[1]), "+f"(c[2]), "+f"(c[3])
                 : "r"(a[0]), "r"(a[1]), "r"(a[2]), "r"(a[3]), "r"(b0), "r"(b1));
}

// half2-as-uint helpers
__device__ __forceinline__ uint32_t h2u(__half2 h) { return *(uint32_t*)&h; }
__device__ __forceinline__ __half2  u2h(uint32_t u) { return *(__half2*)&u; }
__device__ __forceinline__ uint32_t hmul2u(uint32_t a, uint32_t b) {
    return h2u(__hmul2(u2h(a), u2h(b)));
}
__device__ __forceinline__ uint32_t hadd2u(uint32_t a, uint32_t b) {
    return h2u(__hadd2(u2h(a), u2h(b)));
}
__device__ __forceinline__ uint32_t ex2u(uint32_t a) {
    uint32_t d;
    asm("ex2.approx.f16x2 %0, %1;" : "=r"(d) : "r"(a));
    return d;
}
__device__ __forceinline__ uint32_t packh2(float a, float b) {
    __half2 h = __floats2half2_rn(a, b);
    return *(uint32_t*)&h;
}

// ---------------- kernel 0: reset maxima ----------------
__global__ void k0_init() {
    if (threadIdx.x < 8) g_max[threadIdx.x] = -3.4e38f;
}

// ---------------- kernel 1: h, h(fp16), Wh1/Wh2, maxima ----------------
__global__ void k1_prep(const float* __restrict__ x, const float* __restrict__ cw,
                        const float* __restrict__ cb, const float* __restrict__ a) {
    int i = blockIdx.x;
    int d = threadIdx.x;
    float v = x[i * DD + d] * cw[0] + cb[0];
    g_h[i * DD + d] = v;
    g_hh[i * DD + d] = __float2half_rn(v);

    float p[8];
#pragma unroll
    for (int hh = 0; hh < 4; hh++) {
        p[hh]     = v * a[hh * 2 * DD + d];
        p[4 + hh] = v * a[hh * 2 * DD + DD + d];
    }
#pragma unroll
    for (int q = 0; q < 8; q++)
#pragma unroll
        for (int o = 16; o > 0; o >>= 1)
            p[q] += __shfl_xor_sync(0xffffffffu, p[q], o);

    __shared__ float red[8][8];
    int w = d >> 5, lane = d & 31;
    if (lane == 0) {
#pragma unroll
        for (int q = 0; q < 8; q++) red[w][q] = p[q];
    }
    __syncthreads();
    if (d < 8) {
        int q = d;
        float s = 0.f;
#pragma unroll
        for (int ww = 0; ww < 8; ww++) s += red[ww][q];
        if (q < 4) ((float*)g_wh1)[i * 4 + q] = s;
        else       ((float*)g_wh2)[i * 4 + (q - 4)] = s;
        atomicMaxF(&g_max[q], s);
    }
}

// ---------------- kernel 1b: e2s[j,h] = exp(wh2[j,h] - m2[h]/2), packed half2 ----------------
__global__ void __launch_bounds__(256) k1b_e2() {
    int j = blockIdx.x * 256 + threadIdx.x;
    float4 t2 = g_wh2[j];
    float e0 = __expf(t2.x - 0.5f * g_max[4]);
    float e1 = __expf(t2.y - 0.5f * g_max[5]);
    float e2 = __expf(t2.z - 0.5f * g_max[6]);
    float e3 = __expf(t2.w - 0.5f * g_max[7]);
    g_e2h[j] = make_uint2(packh2(e0, e1), packh2(e2, e3));
}

// ---------------- kernel 2: W[i,j] = 1/4 sum_h softmax — f16x2 SIMD, scale-invariant ----------------
// Cache t' = 2^10 * T (softmax scale-invariant; keeps all fp16 values normal).
//   q   = e1s*e2s = exp(s - M/2)            (half2, 2 heads per op)
//   pos (q > th = exp(-M/2)): t' = q*K2,  K2 = exp(-M/2)*2^10   (<= 1024 always)
//   neg:                      t' = C'*ex2(q*K1),  K1 = exp(M/2)*log2e, C' = exp(-1-M)*2^10
//   (selected neg branch has r = q*K1 <= log2e — ex2 arg always small; inf only in discarded lanes)
__global__ void __launch_bounds__(256) k2_weights(const int* __restrict__ adj) {
    int i   = blockIdx.x;
    int tid = threadIdx.x;
    int lane = tid & 31, w = tid >> 5;
    __shared__ float red[8][4];
    __shared__ float Sinv[4];

    float4 t1 = g_wh1[i];
    float wh1f[4] = {t1.x, t1.y, t1.z, t1.w};
    float e1f[4], K1f[4], Cf[4], K2f[4], thf[4];
#pragma unroll
    for (int hh = 0; hh < 4; hh++) {
        float m1 = g_max[hh], m2 = g_max[4 + hh];
        float M = m1 + m2;
        e1f[hh] = __expf(wh1f[hh] - 0.5f * m1);
        K1f[hh] = __expf(0.5f * M) * 1.44269504f;
        Cf[hh]  = __expf(-1.f - M) * 1024.f;
        K2f[hh] = __expf(-0.5f * M) * 1024.f;
        thf[hh] = __expf(-0.5f * M);
    }
    uint32_t e1s01 = packh2(e1f[0], e1f[1]), e1s23 = packh2(e1f[2], e1f[3]);
    uint32_t K101  = packh2(K1f[0], K1f[1]), K123  = packh2(K1f[2], K1f[3]);
    uint32_t C01   = packh2(Cf[0],  Cf[1]),  C23   = packh2(Cf[2],  Cf[3]);
    uint32_t K201  = packh2(K2f[0], K2f[1]), K223  = packh2(K2f[2], K2f[3]);
    uint32_t TH01  = packh2(thf[0], thf[1]), TH23  = packh2(thf[2], thf[3]);

    const int* arow = adj + i * NN;

    // pass A: all masked scaled terms, cached as half2 (heads 01 / heads 23)
    uint32_t tch0[16], tch1[16];
    uint32_t sm01 = 0u, sm23 = 0u;   // half2 zero
#pragma unroll
    for (int it = 0; it < 4; it++) {
        int jb = tid * 4 + it * 1024;
        int4 av = *(const int4*)(arow + jb);
        int aa[4] = {av.x, av.y, av.z, av.w};
#pragma unroll
        for (int u = 0; u < 4; u++) {
            uint2 ep = g_e2h[jb + u];
            uint32_t q01 = hmul2u(e1s01, ep.x);
            uint32_t q23 = hmul2u(e1s23, ep.y);
            uint32_t en01 = ex2u(hmul2u(q01, K101));
            uint32_t en23 = ex2u(hmul2u(q23, K123));
            uint32_t tn01 = hmul2u(en01, C01);
            uint32_t tn23 = hmul2u(en23, C23);
            uint32_t pp01 = hmul2u(q01, K201);
            uint32_t pp23 = hmul2u(q23, K223);
            uint32_t m01 = __hgt2_mask(u2h(q01), u2h(TH01));
            uint32_t m23 = __hgt2_mask(u2h(q23), u2h(TH23));
            uint32_t am = aa[u] > 0 ? 0xFFFFFFFFu : 0u;
            uint32_t t01 = ((((pp01 ^ tn01) & m01) ^ tn01)) & am;
            uint32_t t23 = ((((pp23 ^ tn23) & m23) ^ tn23)) & am;
            tch0[it * 4 + u] = t01;
            tch1[it * 4 + u] = t23;
            sm01 = hadd2u(sm01, t01);
            sm23 = hadd2u(sm23, t23);
        }
    }
    float2 f01 = __half22float2(u2h(sm01));
    float2 f23 = __half22float2(u2h(sm23));
    float sm[4] = {f01.x, f01.y, f23.x, f23.y};
#pragma unroll
    for (int hh = 0; hh < 4; hh++)
#pragma unroll
        for (int o = 16; o > 0; o >>= 1)
            sm[hh] += __shfl_xor_sync(0xffffffffu, sm[hh], o);
    if (lane == 0) {
        red[w][0] = sm[0]; red[w][1] = sm[1]; red[w][2] = sm[2]; red[w][3] = sm[3];
    }
    __syncthreads();
    if (tid < 4) {
        float s = 0.f;
#pragma unroll
        for (int ww = 0; ww < 8; ww++) s += red[ww][tid];
        Sinv[tid] = 0.25f / s;         // scale 2^10 cancels (t' and S' both scaled)
    }
    __syncthreads();
    float inv0 = Sinv[0], inv1 = Sinv[1], inv2 = Sinv[2], inv3 = Sinv[3];

    // pass B: combine cached terms in fp32, write fp16
#pragma unroll
    for (int it = 0; it < 4; it++) {
        int jb = tid * 4 + it * 1024;
        float res[4];
#pragma unroll
        for (int u = 0; u < 4; u++) {
            float2 a01 = __half22float2(u2h(tch0[it * 4 + u]));
            float2 a23 = __half22float2(u2h(tch1[it * 4 + u]));
            res[u] = a01.x * inv0 + a01.y * inv1 + a23.x * inv2 + a23.y * inv3;
        }
        uint2 pk = make_uint2(packh2(res[0], res[1]), packh2(res[2], res[3]));
        *(uint2*)&g_Wh[(size_t)i * NN + jb] = pk;
    }
}

// ---------------- kernel 3: fp16 mma.sync GEMM, cp.async 3-stage, split-K=4 ----------------
// BM=64, BN=64, BK=32; 256 threads (8 warps in 2x4). grid (64, 4, 4) = 1024 CTAs.
#define BK 32
#define NSTAGE 3
#define A_STRIDE 40   // fp16 elems per row (32 + 8 pad) -> 80B
#define B_STRIDE 72   // fp16 elems per row (64 + 8 pad) -> 144B

__global__ void __launch_bounds__(256) k3_gemm() {
    __shared__ __half As[NSTAGE][64][A_STRIDE];
    __shared__ __half Bs[NSTAGE][BK][B_STRIDE];
    int tid = threadIdx.x;
    int w = tid >> 5, lane = tid & 31;
    int wr = w >> 2, wc = w & 3;
    int row0 = blockIdx.x * 64;
    int col0 = blockIdx.y * 64;
    int kbase = blockIdx.z * (NN / 4);

    float acc[2][2][4];
#pragma unroll
    for (int mt = 0; mt < 2; mt++)
#pragma unroll
        for (int nt = 0; nt < 2; nt++)
#pragma unroll
            for (int q = 0; q < 4; q++) acc[mt][nt][q] = 0.f;

    int ar = tid >> 2, aq = tid & 3;
    int br = tid >> 3, bq = tid & 7;

    uint32_t sA[NSTAGE], sB[NSTAGE];
#pragma unroll
    for (int s = 0; s < NSTAGE; s++) {
        sA[s] = smem_u32(&As[s][ar][aq * 8]);
        sB[s] = smem_u32(&Bs[s][br][bq * 8]);
    }

    const int NKS = (NN / 4) / BK;   // 32

#define LOAD_TILE(s, t)                                                           \
    do {                                                                          \
        int k0_ = kbase + (t) * BK;                                               \
        cpasync16(sA[s], &g_Wh[(size_t)(row0 + ar) * NN + k0_ + aq * 8]);         \
        cpasync16(sB[s], &g_hh[(size_t)(k0_ + br) * DD + col0 + bq * 8]);         \
    } while (0)

    LOAD_TILE(0, 0); CP_COMMIT();
    LOAD_TILE(1, 1); CP_COMMIT();

    for (int t = 0; t < NKS; t++) {
        CP_WAIT(1);
        __syncthreads();

        int nxt = t + 2;
        if (nxt < NKS) { LOAD_TILE(nxt % NSTAGE, nxt); }
        CP_COMMIT();

        int buf = t % NSTAGE;
#pragma unroll
        for (int ks = 0; ks < 2; ks++) {
            uint32_t a[2][4];
#pragma unroll
            for (int mt = 0; mt < 2; mt++)
                ldmA(a[mt], smem_u32(&As[buf][wr * 32 + mt * 16 + (lane & 15)]
                                            [ks * 16 + (lane >> 4) * 8]));
            uint32_t b[4];
            ldmBT(b, smem_u32(&Bs[buf][ks * 16 + (lane & 15)]
                                      [wc * 16 + (lane >> 4) * 8]));
#pragma unroll
            for (int mt = 0; mt < 2; mt++)
#pragma unroll
                for (int nt = 0; nt < 2; nt++)
                    mma16816(acc[mt][nt], a[mt], b[nt * 2], b[nt * 2 + 1]);
        }
    }
#undef LOAD_TILE

    // store raw partials (no epilogue)
    float* dst = g_hp[blockIdx.z];
#pragma unroll
    for (int mt = 0; mt < 2; mt++) {
        int rT = row0 + wr * 32 + mt * 16 + (lane >> 2);
        int rB = rT + 8;
#pragma unroll
        for (int nt = 0; nt < 2; nt++) {
            int c = col0 + wc * 16 + nt * 8 + (lane & 3) * 2;
            *(float2*)&dst[rT * DD + c] = make_float2(acc[mt][nt][0], acc[mt][nt][1]);
            *(float2*)&dst[rB * DD + c] = make_float2(acc[mt][nt][2], acc[mt][nt][3]);
        }
    }
}

// ---------------- kernel 4: epilogue (sum partials, elu, row L2-norm, bias) ----------------
__global__ void __launch_bounds__(256) k4_norm(const float* __restrict__ bias,
                                               float* __restrict__ out) {
    __shared__ float red[8];
    __shared__ float s_inv;
    int r = blockIdx.x;
    int c = threadIdx.x;
    int lane = c & 31, w = c >> 5;
    int idx = r * DD + c;

    float hp = (g_hp[0][idx] + g_hp[1][idx]) + (g_hp[2][idx] + g_hp[3][idx]);
    float o = 0.5f * (hp + g_h[idx]);
    o = o > 0.f ? o : (__expf(o) - 1.f);

    float sq = o * o;
#pragma unroll
    for (int off = 16; off > 0; off >>= 1)
        sq += __shfl_xor_sync(0xffffffffu, sq, off);
    if (lane == 0) red[w] = sq;
    __syncthreads();
    if (c < 8) {
        float s = red[c];
#pragma unroll
        for (int off = 4; off > 0; off >>= 1)
            s += __shfl_xor_sync(0xffu, s, off);
        if (c == 0) s_inv = 1.0f / fmaxf(sqrtf(s), 1e-12f);
    }
    __syncthreads();
    out[idx] = o * s_inv + bias[c];
}

// ---------------- launch ----------------
extern "C" void kernel_launch(void* const* d_in, const int* in_sizes, int n_in,
                              void* d_out, int out_size) {
    const float* x    = (const float*)d_in[0];
    const int*   adj  = (const int*)d_in[1];
    const float* cw   = (const float*)d_in[2];
    const float* cb   = (const float*)d_in[3];
    const float* a    = (const float*)d_in[4];
    const float* bias = (const float*)d_in[5];
    float* out = (float*)d_out;

    k0_init<<<1, 32>>>();
    k1_prep<<<NN, 256>>>(x, cw, cb, a);
    k1b_e2<<<NN / 256, 256>>>();
    k2_weights<<<NN, 256>>>(adj);
    dim3 g3(NN / 64, DD / 64, 4);
    k3_gemm<<<g3, 256>>>();
    k4_norm<<<NN, 256>>>(bias, out);
}